// round 17
// baseline (speedup 1.0000x reference)
#include <cuda_runtime.h>
#include <cuda_fp16.h>
#include <cstdint>
#include <cstddef>

// ---------------------------------------------------------------------------
// Bidirectional GRU, B=4096 T=16 I=H=1024.   (R16 champion + epilogue-combine)
//   Gx = X @ [W_izr; W_it]^T  (t-cols get b_it folded in the epilogue)
//   per step, per dir: GEMM h@Wh^T whose epilogue folds gx + combined biases
//   into the r/z columns and b_ht into the t columns, then a slim gate kernel.
// GEMM: fp16 in/out (fp32 accum), mma.sync.m16n8k16 + ldmatrix.x4 + cp.async,
// 128x128 tile, 4 warps (64x64), BK=64, 3 stages, 2 CTAs/SM.
// Gate v4: 5 fp16 uint4 loads, no bias loads, 8 units/thread, spill-free.
// ---------------------------------------------------------------------------

namespace {
constexpr int B_ = 4096, T_ = 16, H_ = 1024;
constexpr int N3 = 3 * H_, K_ = 1024;
constexpr int BM = 128, BN = 128, BK = 64;   // CTA tile; BK in halfs
constexpr int NKT = K_ / BK;                 // 16 k-iterations
constexpr int NST = 3;                       // cp.async stages
constexpr int ROWB = 144;                    // smem row pitch (128B data + 16B pad)
constexpr int A_BYTES = BM * ROWB;           // 18432
constexpr int STAGE = 2 * A_BYTES;           // 36864 (A + B)
constexpr int SMEM_BYTES = NST * STAGE;      // 110592
}

// scratch (static device allocations; no runtime alloc allowed)
__device__ __align__(256) __half g_gx16[(size_t)B_ * T_ * N3];  // x-projections (fp16)
__device__ __align__(256) __half g_gh16[(size_t)2 * B_ * N3];   // combined projections
__device__ __align__(256) __half g_h16[(size_t)4 * B_ * H_];    // fp16 h ping-pong
__device__ __align__(256) __half g_x16[(size_t)B_ * T_ * K_];   // fp16 x
__device__ __align__(256) __half g_wx16[(size_t)N3 * K_];       // [W_izr; W_it] fp16
__device__ __align__(256) __half g_wh16[(size_t)N3 * K_];       // [W_hzr; W_ht] fp16
__device__ __align__(256) float  g_brz[2 * H_];                 // b_izr + b_hzr
__device__ __align__(256) float  g_bti[H_], g_bth[H_];

// ------------------------------ PTX helpers --------------------------------
__device__ __forceinline__ uint32_t smem_u32(const void* p) {
    uint32_t a;
    asm("{.reg .u64 t; cvta.to.shared.u64 t, %1; cvt.u32.u64 %0, t;}" : "=r"(a) : "l"(p));
    return a;
}
__device__ __forceinline__ void cp16(uint32_t d, const void* s) {
    asm volatile("cp.async.cg.shared.global [%0], [%1], 16;" :: "r"(d), "l"(s));
}
__device__ __forceinline__ void cp_commit() { asm volatile("cp.async.commit_group;"); }
template <int N>
__device__ __forceinline__ void cp_wait() { asm volatile("cp.async.wait_group %0;" :: "n"(N)); }

__device__ __forceinline__ void ldsm4(uint32_t& r0, uint32_t& r1, uint32_t& r2, uint32_t& r3,
                                      uint32_t a) {
    asm volatile("ldmatrix.sync.aligned.m8n8.x4.shared.b16 {%0,%1,%2,%3}, [%4];"
                 : "=r"(r0), "=r"(r1), "=r"(r2), "=r"(r3) : "r"(a));
}
__device__ __forceinline__ void mma16816(float c[4], const uint32_t a[4], const uint32_t b[2]) {
    asm volatile(
        "mma.sync.aligned.m16n8k16.row.col.f32.f16.f16.f32 "
        "{%0,%1,%2,%3},{%4,%5,%6,%7},{%8,%9},{%0,%1,%2,%3};"
        : "+f"(c[0]), "+f"(c[1]), "+f"(c[2]), "+f"(c[3])
        : "r"(a[0]), "r"(a[1]), "r"(a[2]), "r"(a[3]), "r"(b[0]), "r"(b[1]));
}
__device__ __forceinline__ float sigmoidf_(float x) { return 1.f / (1.f + expf(-x)); }

// ------------------------------ GEMM kernel --------------------------------
// recur=0: A = g_x16, C = g_gx16; t-columns (n0>=2048) get +b_it.
// recur=1: A = g_h16[(dir*2+phase)], C = g_gh16[dir];
//          r/z columns get +gx(row,time,col) + g_brz[col],
//          t  columns get +g_bth[col-2048].
__global__ __launch_bounds__(128, 2)
void gemm_f16(int dir, int phase, int recur, int time)
{
    extern __shared__ __align__(128) char smem[];
    const uint32_t sb = smem_u32(smem);
    const int tid = threadIdx.x, warp = tid >> 5, lane = tid & 31;
    const int n0 = blockIdx.x * BN, mb = blockIdx.y * BM;

    const __half* A = recur ? g_h16 + (size_t)((dir * 2 + phase) * B_ + mb) * K_
                            : g_x16 + (size_t)mb * K_;
    const __half* W = (recur ? g_wh16 : g_wx16) + (size_t)n0 * K_;
    __half* C = recur ? g_gh16 + (size_t)dir * B_ * N3 : g_gx16;

    // warp tile: 64 x 64  (warp grid 2 x 2)
    const int wm = (warp & 1) * 64, wn = (warp >> 1) * 64;
    const uint32_t aFrag = sb + (uint32_t)(wm + (lane & 15)) * ROWB + ((lane >> 4) & 1) * 16;
    const uint32_t bFrag = sb + A_BYTES +
        (uint32_t)(wn + ((lane >> 4) & 1) * 8 + (lane & 7)) * ROWB + ((lane >> 3) & 1) * 16;

    float acc[4][8][4];
#pragma unroll
    for (int a = 0; a < 4; ++a)
#pragma unroll
        for (int b = 0; b < 8; ++b)
#pragma unroll
            for (int c = 0; c < 4; ++c) acc[a][b][c] = 0.f;

#define FILL(S, KT)                                                           \
    {                                                                         \
        _Pragma("unroll")                                                     \
        for (int i = 0; i < 8; ++i) {                                         \
            int c = tid + 128 * i;                                            \
            int row = c >> 3, col = c & 7;                                    \
            uint32_t d = sb + (S) * STAGE + row * ROWB + col * 16;            \
            cp16(d, A + (size_t)row * K_ + (KT) * BK + col * 8);              \
            cp16(d + A_BYTES, W + (size_t)row * K_ + (KT) * BK + col * 8);    \
        }                                                                     \
    }

#pragma unroll
    for (int s = 0; s < NST - 1; ++s) { FILL(s, s); cp_commit(); }

    int st = 0;
    for (int kt = 0; kt < NKT; ++kt) {
        cp_wait<NST - 2>();
        __syncthreads();
        if (kt + NST - 1 < NKT) {
            int fs = st + 2; if (fs >= NST) fs -= NST;
            FILL(fs, kt + NST - 1);
        }
        cp_commit();

        const uint32_t aS = aFrag + st * STAGE;
        const uint32_t bS = bFrag + st * STAGE;
#pragma unroll
        for (int ks = 0; ks < 4; ++ks) {
            uint32_t af[4][4], bf[8][2];
#pragma unroll
            for (int mi = 0; mi < 4; ++mi)
                ldsm4(af[mi][0], af[mi][1], af[mi][2], af[mi][3],
                      aS + mi * 16 * ROWB + ks * 32);
#pragma unroll
            for (int nj = 0; nj < 4; ++nj)
                ldsm4(bf[2 * nj][0], bf[2 * nj][1], bf[2 * nj + 1][0], bf[2 * nj + 1][1],
                      bS + nj * 16 * ROWB + ks * 32);
#pragma unroll
            for (int mi = 0; mi < 4; ++mi)
#pragma unroll
                for (int ni = 0; ni < 8; ++ni)
                    mma16816(acc[mi][ni], af[mi], bf[ni]);
        }
        if (++st == NST) st = 0;
    }
#undef FILL

    // ------------------------------ epilogue -------------------------------
    const int cBase = n0 + wn + (lane & 3) * 2;
    const int rBase = mb + wm + (lane >> 2);
    const bool isT = (n0 >= 2 * H_);          // uniform per CTA

    if (recur) {
#pragma unroll
        for (int mi = 0; mi < 4; ++mi) {
            const int r0 = rBase + mi * 16;
#pragma unroll
            for (int ni = 0; ni < 8; ++ni) {
                const int c = cBase + ni * 8;
                float a0 = acc[mi][ni][0], a1 = acc[mi][ni][1];
                float a2 = acc[mi][ni][2], a3 = acc[mi][ni][3];
                if (!isT) {
                    float2 bz = *(const float2*)(g_brz + c);
                    float2 f0 = __half22float2(*(const __half2*)(
                        g_gx16 + ((size_t)r0 * T_ + time) * N3 + c));
                    float2 f1 = __half22float2(*(const __half2*)(
                        g_gx16 + ((size_t)(r0 + 8) * T_ + time) * N3 + c));
                    a0 += f0.x + bz.x; a1 += f0.y + bz.y;
                    a2 += f1.x + bz.x; a3 += f1.y + bz.y;
                } else {
                    float2 bt = *(const float2*)(g_bth + c - 2 * H_);
                    a0 += bt.x; a1 += bt.y; a2 += bt.x; a3 += bt.y;
                }
                __half* crow = C + (size_t)r0 * N3 + c;
                *reinterpret_cast<__half2*>(crow) = __floats2half2_rn(a0, a1);
                *reinterpret_cast<__half2*>(crow + (size_t)8 * N3) = __floats2half2_rn(a2, a3);
            }
        }
    } else {
#pragma unroll
        for (int mi = 0; mi < 4; ++mi) {
            const int r0 = rBase + mi * 16;
#pragma unroll
            for (int ni = 0; ni < 8; ++ni) {
                const int c = cBase + ni * 8;
                float a0 = acc[mi][ni][0], a1 = acc[mi][ni][1];
                float a2 = acc[mi][ni][2], a3 = acc[mi][ni][3];
                if (isT) {
                    float2 bt = *(const float2*)(g_bti + c - 2 * H_);
                    a0 += bt.x; a1 += bt.y; a2 += bt.x; a3 += bt.y;
                }
                __half* crow = C + (size_t)r0 * N3 + c;
                *reinterpret_cast<__half2*>(crow) = __floats2half2_rn(a0, a1);
                *reinterpret_cast<__half2*>(crow + (size_t)8 * N3) = __floats2half2_rn(a2, a3);
            }
        }
    }
}

// -------------------- gate kernel v4 (slim, 8-wide) -------------------------
// gh r cols = pre-activation r; gh z cols = pre-activation z;
// gh t cols = ght + bth; gx t cols = gxt + bti.
__global__ __launch_bounds__(256)
void gate_kernel(float* __restrict__ out, int d, int s)
{
    const int idx = blockIdx.x * blockDim.x + threadIdx.x;   // B*H/8 threads
    const int j8  = idx << 3;
    const int b   = j8 >> 10;
    const int j   = j8 & (H_ - 1);
    const int time = (d == 0) ? s : (T_ - 1 - s);
    const int tout = (d == 0) ? (T_ - 1 - s) : s;

    const __half* gx = g_gx16 + ((size_t)b * T_ + time) * N3 + j;
    const __half* gh = g_gh16 + (size_t)d * B_ * N3 + (size_t)b * N3 + j;
    const size_t hprev = ((size_t)d * 2 + (s & 1)) * B_ * H_ + (size_t)b * H_ + j;
    const size_t hnext = ((size_t)d * 2 + ((s + 1) & 1)) * B_ * H_ + (size_t)b * H_ + j;

    uint4 uhr = *(const uint4*)(gh);              // r pre-activation
    uint4 uhz = *(const uint4*)(gh + H_);         // z pre-activation
    uint4 uht = *(const uint4*)(gh + 2 * H_);     // ght + bth
    uint4 uxt = *(const uint4*)(gx + 2 * H_);     // gxt + bti
    uint4 uhp = *(const uint4*)(g_h16 + hprev);

#define F2(u) __half22float2(*reinterpret_cast<__half2*>(&(u)))
    float2 pr0 = F2(uhr.x), pr1 = F2(uhr.y), pr2 = F2(uhr.z), pr3 = F2(uhr.w);
    float2 pz0 = F2(uhz.x), pz1 = F2(uhz.y), pz2 = F2(uhz.z), pz3 = F2(uhz.w);
    float2 ct0 = F2(uht.x), ct1 = F2(uht.y), ct2 = F2(uht.z), ct3 = F2(uht.w);
    float2 xt0 = F2(uxt.x), xt1 = F2(uxt.y), xt2 = F2(uxt.z), xt3 = F2(uxt.w);
    float2 hp0 = F2(uhp.x), hp1 = F2(uhp.y), hp2 = F2(uhp.z), hp3 = F2(uhp.w);
#undef F2

    float nh0, nh1, nh2, nh3, nh4, nh5, nh6, nh7;
#define GATE(NH, PR, PZ, XT, CT, HV)                                        \
    {                                                                       \
        float rg = sigmoidf_(PR);                                           \
        float zg = sigmoidf_(PZ);                                           \
        float tg = tanhf((XT) + rg * (CT));                                 \
        NH = zg * tg + (1.f - zg) * (HV);                                   \
    }
    GATE(nh0, pr0.x, pz0.x, xt0.x, ct0.x, hp0.x)
    GATE(nh1, pr0.y, pz0.y, xt0.y, ct0.y, hp0.y)
    GATE(nh2, pr1.x, pz1.x, xt1.x, ct1.x, hp1.x)
    GATE(nh3, pr1.y, pz1.y, xt1.y, ct1.y, hp1.y)
    GATE(nh4, pr2.x, pz2.x, xt2.x, ct2.x, hp2.x)
    GATE(nh5, pr2.y, pz2.y, xt2.y, ct2.y, hp2.y)
    GATE(nh6, pr3.x, pz3.x, xt3.x, ct3.x, hp3.x)
    GATE(nh7, pr3.y, pz3.y, xt3.y, ct3.y, hp3.y)
#undef GATE

    __half2 p0 = __floats2half2_rn(nh0, nh1);
    __half2 p1 = __floats2half2_rn(nh2, nh3);
    __half2 p2 = __floats2half2_rn(nh4, nh5);
    __half2 p3 = __floats2half2_rn(nh6, nh7);
    uint4 u16;
    u16.x = *reinterpret_cast<uint32_t*>(&p0);
    u16.y = *reinterpret_cast<uint32_t*>(&p1);
    u16.z = *reinterpret_cast<uint32_t*>(&p2);
    u16.w = *reinterpret_cast<uint32_t*>(&p3);
    *reinterpret_cast<uint4*>(g_h16 + hnext) = u16;

    float* op = out + ((size_t)b * T_ + tout) * (2 * H_) + (size_t)d * H_ + j;
    *(float4*)(op)     = make_float4(nh0, nh1, nh2, nh3);
    *(float4*)(op + 4) = make_float4(nh4, nh5, nh6, nh7);
}

// ------------------------------ small kernels ------------------------------
__global__ void cvt16(const float* __restrict__ s, __half* __restrict__ d, int n4)
{
    int i = blockIdx.x * blockDim.x + threadIdx.x;
    if (i < n4) {
        float4 v = reinterpret_cast<const float4*>(s)[i];
        __half2 p0 = __floats2half2_rn(v.x, v.y);
        __half2 p1 = __floats2half2_rn(v.z, v.w);
        uint2 u; u.x = *reinterpret_cast<uint32_t*>(&p0); u.y = *reinterpret_cast<uint32_t*>(&p1);
        reinterpret_cast<uint2*>(d)[i] = u;
    }
}

__global__ void bias_prep(const float* __restrict__ b_izr, const float* __restrict__ b_hzr,
                          const float* __restrict__ b_it,  const float* __restrict__ b_ht)
{
    int j = blockIdx.x * blockDim.x + threadIdx.x;
    if (j < 2 * H_) g_brz[j] = b_izr[j] + b_hzr[j];
    if (j < H_) { g_bti[j] = b_it[j]; g_bth[j] = b_ht[j]; }
}

__global__ void init_h(const float* __restrict__ h0, const float* __restrict__ bih0)
{
    size_t i = (size_t)blockIdx.x * blockDim.x + threadIdx.x;
    if (i < (size_t)B_ * H_) {
        g_h16[i] = __float2half_rn(h0[i]);                         // dir 0, phase 0
        g_h16[(size_t)2 * B_ * H_ + i] = __float2half_rn(bih0[i]); // dir 1, phase 0
    }
}

// ------------------------------ host side ----------------------------------
extern "C" void kernel_launch(void* const* d_in, const int* in_sizes, int n_in,
                              void* d_out, int out_size)
{
    const float* x     = (const float*)d_in[0];
    const float* h0    = (const float*)d_in[1];
    const float* bih0  = (const float*)d_in[2];
    const float* W_izr = (const float*)d_in[3];
    const float* b_izr = (const float*)d_in[4];
    const float* W_hzr = (const float*)d_in[5];
    const float* b_hzr = (const float*)d_in[6];
    const float* W_it  = (const float*)d_in[7];
    const float* b_it  = (const float*)d_in[8];
    const float* W_ht  = (const float*)d_in[9];
    const float* b_ht  = (const float*)d_in[10];
    float* out = (float*)d_out;
    (void)in_sizes; (void)n_in; (void)out_size;

    void *p_x16 = nullptr, *p_wx = nullptr, *p_wh = nullptr;
    cudaGetSymbolAddress(&p_x16, g_x16);
    cudaGetSymbolAddress(&p_wx, g_wx16);
    cudaGetSymbolAddress(&p_wh, g_wh16);

    cudaFuncSetAttribute(gemm_f16, cudaFuncAttributeMaxDynamicSharedMemorySize, SMEM_BYTES);

    // streams/events created ONCE (deterministic; keeps mem baseline stable)
    static cudaStream_t st2 = nullptr;
    static cudaEvent_t evFork, evPrep2, evGx, evJoin;
    if (st2 == nullptr) {
        cudaStreamCreateWithFlags(&st2, cudaStreamNonBlocking);
        cudaEventCreateWithFlags(&evFork,  cudaEventDisableTiming);
        cudaEventCreateWithFlags(&evPrep2, cudaEventDisableTiming);
        cudaEventCreateWithFlags(&evGx,    cudaEventDisableTiming);
        cudaEventCreateWithFlags(&evJoin,  cudaEventDisableTiming);
    }

    cudaEventRecord(evFork, 0);
    cudaStreamWaitEvent(st2, evFork, 0);

    // prep split across streams (bias_prep must precede the Gx GEMM: stream 0)
    const int WN4 = 2 * H_ * K_ / 4, WN4b = H_ * K_ / 4, XN4 = B_ * T_ * K_ / 4;
    bias_prep<<<8, 256>>>(b_izr, b_hzr, b_it, b_ht);
    cvt16<<<(WN4 + 255) / 256, 256>>>(W_izr, (__half*)p_wx, WN4);
    cvt16<<<(WN4b + 255) / 256, 256>>>(W_it, (__half*)p_wx + (size_t)2 * H_ * K_, WN4b);
    cvt16<<<(XN4 + 255) / 256, 256>>>(x, (__half*)p_x16, XN4);
    cvt16<<<(WN4 + 255) / 256, 256, 0, st2>>>(W_hzr, (__half*)p_wh, WN4);
    cvt16<<<(WN4b + 255) / 256, 256, 0, st2>>>(W_ht, (__half*)p_wh + (size_t)2 * H_ * K_, WN4b);
    init_h<<<(B_ * H_ + 255) / 256, 256, 0, st2>>>(h0, bih0);
    cudaEventRecord(evPrep2, st2);

    // Gx = X @ [W_izr; W_it]^T over all (b, t)   (stream 0)
    gemm_f16<<<dim3(N3 / BN, (B_ * T_) / BM), 128, SMEM_BYTES>>>(0, 0, 0, 0);
    cudaEventRecord(evGx, 0);

    // stream 0's chain needs wh16/h16 (prep on st2); st2's chain needs Gx
    cudaStreamWaitEvent(0, evPrep2, 0);
    cudaStreamWaitEvent(st2, evGx, 0);

    const int GATE_BLKS = (B_ * H_) / (256 * 8);
    for (int s = 0; s < T_; ++s) {
        const int t0 = s, t1 = T_ - 1 - s;
        gemm_f16<<<dim3(N3 / BN, B_ / BM), 128, SMEM_BYTES>>>(0, s & 1, 1, t0);
        gemm_f16<<<dim3(N3 / BN, B_ / BM), 128, SMEM_BYTES, st2>>>(1, s & 1, 1, t1);
        gate_kernel<<<GATE_BLKS, 256>>>(out, 0, s);
        gate_kernel<<<GATE_BLKS, 256, 0, st2>>>(out, 1, s);
    }

    // join st2 back into the captured stream
    cudaEventRecord(evJoin, st2);
    cudaStreamWaitEvent(0, evJoin, 0);
}